// round 1
// baseline (speedup 1.0000x reference)
#include <cuda_runtime.h>
#include <math.h>

#define B_     16
#define L_     784
#define D_     384
#define H_     8
#define QK_    32
#define VD_    128
#define EH_    192          // per-head qkv width
#define QKVN_  1536
#define RESI_  625
#define CK_    49           // keys per flash chunk (784 = 16*49)
#define QT_    64           // queries per flash block

// ---------------- scratch (static device globals; no runtime alloc) --------
__device__ float g_qkv[(size_t)B_ * L_ * QKVN_];        // 77 MB
__device__ float g_abg[(size_t)H_ * RESI_ * RESI_];     // 12.5 MB
__device__ float g_bias[(size_t)H_ * L_ * L_];          // 19.7 MB
__device__ float g_ao[(size_t)B_ * L_ * H_ * VD_];      // 51 MB
__device__ float g_iw[L_ * 4];
__device__ int   g_ii[L_ * 4];

// ---------------- K0: bicubic interp weights/indices (784 rows x 4) --------
__global__ void build_interp_kernel() {
    int o = blockIdx.x * blockDim.x + threadIdx.x;
    if (o >= L_) return;
    const float a = -0.75f;
    float scale = (float)RESI_ / (float)L_;
    float src = ((float)o + 0.5f) * scale - 0.5f;
    float f = floorf(src);
    float t = src - f;
    float xs[4] = { t + 1.0f, t, 1.0f - t, 2.0f - t };
#pragma unroll
    for (int i = 0; i < 4; i++) {
        float ax = fabsf(xs[i]);
        float w1 = ((a + 2.0f) * ax - (a + 3.0f)) * ax * ax + 1.0f;
        float w2 = a * (((ax - 5.0f) * ax + 8.0f) * ax - 4.0f);
        float w = (ax <= 1.0f) ? w1 : ((ax < 2.0f) ? w2 : 0.0f);
        g_iw[o * 4 + i] = w;
        int id = (int)f - 1 + i;
        id = id < 0 ? 0 : (id > RESI_ - 1 ? RESI_ - 1 : id);
        g_ii[o * 4 + i] = id;
    }
}

// ---------------- K1: ab gather: abg[h,i,j] = ab_table[h, bias_idxs[i,j]] ---
__global__ void gather_ab_kernel(const float* __restrict__ ab_table,
                                 const int* __restrict__ bias_idxs) {
    int i = blockIdx.x * blockDim.x + threadIdx.x;
    const int total = H_ * RESI_ * RESI_;
    if (i >= total) return;
    int h = i / (RESI_ * RESI_);
    int ij = i - h * (RESI_ * RESI_);
    g_abg[i] = ab_table[h * RESI_ + bias_idxs[ij]];
}

// ---------------- K2: bias[h,o,p] = sum_{a,b} wo[a]*wp[b]*abg[h,io[a],ip[b]]
__global__ void build_bias_kernel() {
    int i = blockIdx.x * blockDim.x + threadIdx.x;
    const int total = H_ * L_ * L_;
    if (i >= total) return;
    int h = i / (L_ * L_);
    int r = i - h * (L_ * L_);
    int o = r / L_;
    int p = r - o * L_;
    const float* __restrict__ abh = g_abg + (size_t)h * RESI_ * RESI_;
    float wp[4]; int ip[4];
#pragma unroll
    for (int bb = 0; bb < 4; bb++) { wp[bb] = g_iw[p * 4 + bb]; ip[bb] = g_ii[p * 4 + bb]; }
    float s = 0.f;
#pragma unroll
    for (int aa = 0; aa < 4; aa++) {
        float wa = g_iw[o * 4 + aa];
        const float* row = abh + (size_t)g_ii[o * 4 + aa] * RESI_;
        float sb = 0.f;
#pragma unroll
        for (int bb = 0; bb < 4; bb++) sb = fmaf(wp[bb], __ldg(row + ip[bb]), sb);
        s = fmaf(wa, sb, s);
    }
    g_bias[i] = s;
}

// ---------------- K3/K5: C[M,N] = A[M,K] @ W[N,K]^T (+ bias over N) --------
// BM=BN=128, BK=16, 256 threads, 8x8 microtile. M%128==0, N%128==0, K%16==0.
template <bool ADD_BIAS>
__global__ __launch_bounds__(256) void sgemm_nt_kernel(
    const float* __restrict__ A, const float* __restrict__ W,
    const float* __restrict__ bias, float* __restrict__ C,
    int M, int N, int K)
{
    __shared__ float As[16][132];
    __shared__ float Bs[16][132];
    int tid = threadIdx.x;
    int bm = blockIdx.y * 128;
    int bn = blockIdx.x * 128;
    int lrow = tid >> 2;             // 0..63
    int lcol = (tid & 3) << 2;       // 0,4,8,12
    int ty = tid >> 4;               // 0..15
    int tx = tid & 15;               // 0..15
    const float* Ab = A + (size_t)bm * K;
    const float* Wb = W + (size_t)bn * K;
    float acc[8][8];
#pragma unroll
    for (int i = 0; i < 8; i++)
#pragma unroll
        for (int j = 0; j < 8; j++) acc[i][j] = 0.f;

    for (int k0 = 0; k0 < K; k0 += 16) {
#pragma unroll
        for (int rr = 0; rr < 2; rr++) {
            int rw = lrow + rr * 64;
            float4 va = *(const float4*)(Ab + (size_t)rw * K + k0 + lcol);
            As[lcol + 0][rw] = va.x; As[lcol + 1][rw] = va.y;
            As[lcol + 2][rw] = va.z; As[lcol + 3][rw] = va.w;
            float4 vb = *(const float4*)(Wb + (size_t)rw * K + k0 + lcol);
            Bs[lcol + 0][rw] = vb.x; Bs[lcol + 1][rw] = vb.y;
            Bs[lcol + 2][rw] = vb.z; Bs[lcol + 3][rw] = vb.w;
        }
        __syncthreads();
#pragma unroll
        for (int k = 0; k < 16; k++) {
            float4 a0 = *(const float4*)&As[k][ty * 8];
            float4 a1 = *(const float4*)&As[k][ty * 8 + 4];
            float4 b0 = *(const float4*)&Bs[k][tx * 8];
            float4 b1 = *(const float4*)&Bs[k][tx * 8 + 4];
            float ra[8] = { a0.x, a0.y, a0.z, a0.w, a1.x, a1.y, a1.z, a1.w };
            float rb[8] = { b0.x, b0.y, b0.z, b0.w, b1.x, b1.y, b1.z, b1.w };
#pragma unroll
            for (int i = 0; i < 8; i++)
#pragma unroll
                for (int j = 0; j < 8; j++) acc[i][j] = fmaf(ra[i], rb[j], acc[i][j]);
        }
        __syncthreads();
    }
#pragma unroll
    for (int i = 0; i < 8; i++) {
        float* crow = C + (size_t)(bm + ty * 8 + i) * N + bn + tx * 8;
#pragma unroll
        for (int j4 = 0; j4 < 2; j4++) {
            float4 v;
            v.x = acc[i][j4 * 4 + 0]; v.y = acc[i][j4 * 4 + 1];
            v.z = acc[i][j4 * 4 + 2]; v.w = acc[i][j4 * 4 + 3];
            if (ADD_BIAS) {
                v.x += bias[bn + tx * 8 + j4 * 4 + 0];
                v.y += bias[bn + tx * 8 + j4 * 4 + 1];
                v.z += bias[bn + tx * 8 + j4 * 4 + 2];
                v.w += bias[bn + tx * 8 + j4 * 4 + 3];
            }
            *(float4*)(crow + j4 * 4) = v;
        }
    }
}

// ---------------- K4: fused flash attention with additive bias -------------
// Block = (qtile, head, batch), 128 threads: thread t -> query row (t&63),
// V-half (t>>6). Scores computed cooperatively into smem (no redundant QK).
__global__ __launch_bounds__(128) void flash_attn_kernel() {
    __shared__ float Ks[CK_][QK_];    //  6.3 KB
    __shared__ float Vs[CK_][VD_];    // 25.1 KB
    __shared__ float Ss[QT_][CK_];    // 12.5 KB  (49 % 32 = 17, odd -> conflict-free)
    int t = threadIdx.x;
    int half = t >> 6;
    int r = t & 63;
    int b = blockIdx.z, h = blockIdx.y;
    int qrow = blockIdx.x * QT_ + r;
    bool valid = qrow < L_;
    const float scale = 0.17677669529663687f;   // 32^-0.5

    float q[QK_];
    if (valid) {
        const float4* qp = (const float4*)(g_qkv + (size_t)(b * L_ + qrow) * QKVN_ + h * EH_);
#pragma unroll
        for (int i = 0; i < 8; i++) {
            float4 v = qp[i];
            q[i * 4 + 0] = v.x; q[i * 4 + 1] = v.y; q[i * 4 + 2] = v.z; q[i * 4 + 3] = v.w;
        }
    }
    float acc[64];
#pragma unroll
    for (int i = 0; i < 64; i++) acc[i] = 0.f;
    float m = -1e30f, l = 0.f;

    for (int kc = 0; kc < L_ / CK_; kc++) {
        int j0 = kc * CK_;
        // cooperative loads: K chunk (49x32) and V chunk (49x128), float4
        for (int i = t; i < CK_ * QK_ / 4; i += 128) {
            int jj = i >> 3; int cc = (i & 7) << 2;
            *(float4*)&Ks[jj][cc] =
                *(const float4*)(g_qkv + (size_t)(b * L_ + j0 + jj) * QKVN_ + h * EH_ + QK_ + cc);
        }
        for (int i = t; i < CK_ * VD_ / 4; i += 128) {
            int jj = i >> 5; int cc = (i & 31) << 2;
            *(float4*)&Vs[jj][cc] =
                *(const float4*)(g_qkv + (size_t)(b * L_ + j0 + jj) * QKVN_ + h * EH_ + 2 * QK_ + cc);
        }
        __syncthreads();

        // scores: thread (r, half) computes its row's keys with parity == half
        if (valid) {
            const float* brow = g_bias + ((size_t)h * L_ + qrow) * L_ + j0;
            for (int j = half; j < CK_; j += 2) {
                float d = 0.f;
#pragma unroll
                for (int c4 = 0; c4 < 8; c4++) {
                    float4 kk = *(const float4*)&Ks[j][c4 * 4];
                    d = fmaf(q[c4 * 4 + 0], kk.x, d);
                    d = fmaf(q[c4 * 4 + 1], kk.y, d);
                    d = fmaf(q[c4 * 4 + 2], kk.z, d);
                    d = fmaf(q[c4 * 4 + 3], kk.w, d);
                }
                Ss[r][j] = fmaf(d, scale, __ldg(brow + j));
            }
        }
        __syncthreads();

        // online softmax + PV accumulate (each thread: full row stats, half of V dims)
        if (valid) {
            float mc = -1e30f;
#pragma unroll
            for (int j = 0; j < CK_; j++) mc = fmaxf(mc, Ss[r][j]);
            float mnew = fmaxf(m, mc);
            float corr = __expf(m - mnew);
            l *= corr;
#pragma unroll
            for (int i = 0; i < 64; i++) acc[i] *= corr;
#pragma unroll 1
            for (int j = 0; j < CK_; j++) {
                float p = __expf(Ss[r][j] - mnew);
                l += p;
                const float4* vr = (const float4*)&Vs[j][half * 64];
#pragma unroll
                for (int d4 = 0; d4 < 16; d4++) {
                    float4 v = vr[d4];
                    acc[d4 * 4 + 0] = fmaf(p, v.x, acc[d4 * 4 + 0]);
                    acc[d4 * 4 + 1] = fmaf(p, v.y, acc[d4 * 4 + 1]);
                    acc[d4 * 4 + 2] = fmaf(p, v.z, acc[d4 * 4 + 2]);
                    acc[d4 * 4 + 3] = fmaf(p, v.w, acc[d4 * 4 + 3]);
                }
            }
            m = mnew;
        }
        __syncthreads();
    }

    if (valid) {
        float inv = 1.0f / l;
        float* op = g_ao + (size_t)(b * L_ + qrow) * (H_ * VD_) + h * VD_ + half * 64;
#pragma unroll
        for (int d4 = 0; d4 < 16; d4++) {
            float4 v;
            v.x = acc[d4 * 4 + 0] * inv; v.y = acc[d4 * 4 + 1] * inv;
            v.z = acc[d4 * 4 + 2] * inv; v.w = acc[d4 * 4 + 3] * inv;
            *(float4*)(op + d4 * 4) = v;
        }
    }
}

// ---------------- launch ---------------------------------------------------
extern "C" void kernel_launch(void* const* d_in, const int* in_sizes, int n_in,
                              void* d_out, int out_size) {
    const float* x         = (const float*)d_in[0];   // (16,784,384)
    const float* Wqkv      = (const float*)d_in[1];   // (1536,384)
    const float* Wproj     = (const float*)d_in[2];   // (384,1024)
    const float* bproj     = (const float*)d_in[3];   // (384,)
    const float* ab_table  = (const float*)d_in[4];   // (8,625)
    const int*   bias_idxs = (const int*)d_in[5];     // (625,625)
    float* out = (float*)d_out;

    void* pqkv = nullptr; cudaGetSymbolAddress(&pqkv, g_qkv);
    void* pao  = nullptr; cudaGetSymbolAddress(&pao,  g_ao);

    build_interp_kernel<<<1, 1024>>>();

    const int totAb = H_ * RESI_ * RESI_;
    gather_ab_kernel<<<(totAb + 255) / 256, 256>>>(ab_table, bias_idxs);

    build_bias_kernel<<<(H_ * L_ * L_) / 256, 256>>>();   // 4917248 / 256 exact

    dim3 gqkv(QKVN_ / 128, (B_ * L_) / 128);
    sgemm_nt_kernel<false><<<gqkv, 256>>>(x, Wqkv, nullptr, (float*)pqkv,
                                          B_ * L_, QKVN_, D_);

    dim3 gatt((L_ + QT_ - 1) / QT_, H_, B_);
    flash_attn_kernel<<<gatt, 128>>>();

    dim3 gproj(D_ / 128, (B_ * L_) / 128);
    sgemm_nt_kernel<true><<<gproj, 256>>>((const float*)pao, Wproj, bproj, out,
                                          B_ * L_, D_, H_ * VD_);
}

// round 2
// speedup vs baseline: 1.0519x; 1.0519x over previous
#include <cuda_runtime.h>
#include <math.h>

#define B_     16
#define L_     784
#define D_     384
#define H_     8
#define QK_    32
#define VD_    128
#define EH_    192          // per-head qkv width
#define QKVN_  1536
#define RESI_  625
#define CK_    49           // keys per flash chunk (784 = 16*49)
#define QT_    64           // queries per flash block

typedef unsigned long long u64;

// ---------------- packed fp32x2 helpers (sm_103a) ---------------------------
__device__ __forceinline__ u64 pk2(float a, float b) {
    u64 r; asm("mov.b64 %0, {%1, %2};" : "=l"(r) : "f"(a), "f"(b)); return r;
}
__device__ __forceinline__ void upk2(u64 v, float& a, float& b) {
    asm("mov.b64 {%0, %1}, %2;" : "=f"(a), "=f"(b) : "l"(v));
}
__device__ __forceinline__ void ffma2(u64& d, u64 a, u64 b) {
    asm("fma.rn.f32x2 %0, %1, %2, %0;" : "+l"(d) : "l"(a), "l"(b));
}
__device__ __forceinline__ void fmul2(u64& d, u64 a) {
    asm("mul.rn.f32x2 %0, %0, %1;" : "+l"(d) : "l"(a));
}

// ---------------- scratch (static device globals; no runtime alloc) --------
__device__ float g_qkv[(size_t)B_ * L_ * QKVN_];        // 77 MB
__device__ float g_abg[(size_t)H_ * RESI_ * RESI_];     // 12.5 MB
__device__ float g_bias[(size_t)H_ * L_ * L_];          // 19.7 MB
__device__ float g_ao[(size_t)B_ * L_ * H_ * VD_];      // 51 MB
__device__ float g_iw[L_ * 4];
__device__ int   g_ii[L_ * 4];

// ---------------- K0: bicubic interp weights/indices (784 rows x 4) --------
__global__ void build_interp_kernel() {
    int o = blockIdx.x * blockDim.x + threadIdx.x;
    if (o >= L_) return;
    const float a = -0.75f;
    float scale = (float)RESI_ / (float)L_;
    float src = ((float)o + 0.5f) * scale - 0.5f;
    float f = floorf(src);
    float t = src - f;
    float xs[4] = { t + 1.0f, t, 1.0f - t, 2.0f - t };
#pragma unroll
    for (int i = 0; i < 4; i++) {
        float ax = fabsf(xs[i]);
        float w1 = ((a + 2.0f) * ax - (a + 3.0f)) * ax * ax + 1.0f;
        float w2 = a * (((ax - 5.0f) * ax + 8.0f) * ax - 4.0f);
        float w = (ax <= 1.0f) ? w1 : ((ax < 2.0f) ? w2 : 0.0f);
        g_iw[o * 4 + i] = w;
        int id = (int)f - 1 + i;
        id = id < 0 ? 0 : (id > RESI_ - 1 ? RESI_ - 1 : id);
        g_ii[o * 4 + i] = id;
    }
}

// ---------------- K1: ab gather: abg[h,i,j] = ab_table[h, bias_idxs[i,j]] ---
__global__ void gather_ab_kernel(const float* __restrict__ ab_table,
                                 const int* __restrict__ bias_idxs) {
    int i = blockIdx.x * blockDim.x + threadIdx.x;
    const int total = H_ * RESI_ * RESI_;
    if (i >= total) return;
    int h = i / (RESI_ * RESI_);
    int ij = i - h * (RESI_ * RESI_);
    g_abg[i] = ab_table[h * RESI_ + bias_idxs[ij]];
}

// ---------------- K2: bias[h,o,p] = sum_{a,b} wo[a]*wp[b]*abg[h,io[a],ip[b]]
__global__ void build_bias_kernel() {
    int i = blockIdx.x * blockDim.x + threadIdx.x;
    const int total = H_ * L_ * L_;
    if (i >= total) return;
    int h = i / (L_ * L_);
    int r = i - h * (L_ * L_);
    int o = r / L_;
    int p = r - o * L_;
    const float* __restrict__ abh = g_abg + (size_t)h * RESI_ * RESI_;
    float wp[4]; int ip[4];
#pragma unroll
    for (int bb = 0; bb < 4; bb++) { wp[bb] = g_iw[p * 4 + bb]; ip[bb] = g_ii[p * 4 + bb]; }
    float s = 0.f;
#pragma unroll
    for (int aa = 0; aa < 4; aa++) {
        float wa = g_iw[o * 4 + aa];
        const float* row = abh + (size_t)g_ii[o * 4 + aa] * RESI_;
        float sb = 0.f;
#pragma unroll
        for (int bb = 0; bb < 4; bb++) sb = fmaf(wp[bb], __ldg(row + ip[bb]), sb);
        s = fmaf(wa, sb, s);
    }
    g_bias[i] = s;
}

// ---------------- K3/K5: C[M,N] = A[M,K] @ W[N,K]^T (+ bias over N) --------
// BM=BN=128, BK=16, 256 threads, 8x8 microtile, f32x2 packed FMA.
template <bool ADD_BIAS>
__global__ __launch_bounds__(256) void sgemm_nt_kernel(
    const float* __restrict__ A, const float* __restrict__ W,
    const float* __restrict__ bias, float* __restrict__ C,
    int M, int N, int K)
{
    __shared__ __align__(16) float As[16][132];
    __shared__ __align__(16) float Bs[16][132];
    int tid = threadIdx.x;
    int bm = blockIdx.y * 128;
    int bn = blockIdx.x * 128;
    int lrow = tid >> 2;             // 0..63
    int lcol = (tid & 3) << 2;       // 0,4,8,12
    int ty = tid >> 4;               // 0..15
    int tx = tid & 15;               // 0..15
    const float* Ab = A + (size_t)bm * K;
    const float* Wb = W + (size_t)bn * K;
    u64 acc2[8][4];
#pragma unroll
    for (int i = 0; i < 8; i++)
#pragma unroll
        for (int j = 0; j < 4; j++) acc2[i][j] = 0ull;

    for (int k0 = 0; k0 < K; k0 += 16) {
#pragma unroll
        for (int rr = 0; rr < 2; rr++) {
            int rw = lrow + rr * 64;
            float4 va = *(const float4*)(Ab + (size_t)rw * K + k0 + lcol);
            As[lcol + 0][rw] = va.x; As[lcol + 1][rw] = va.y;
            As[lcol + 2][rw] = va.z; As[lcol + 3][rw] = va.w;
            float4 vb = *(const float4*)(Wb + (size_t)rw * K + k0 + lcol);
            Bs[lcol + 0][rw] = vb.x; Bs[lcol + 1][rw] = vb.y;
            Bs[lcol + 2][rw] = vb.z; Bs[lcol + 3][rw] = vb.w;
        }
        __syncthreads();
#pragma unroll
        for (int k = 0; k < 16; k++) {
            float4 a0 = *(const float4*)&As[k][ty * 8];
            float4 a1 = *(const float4*)&As[k][ty * 8 + 4];
            float4 b0 = *(const float4*)&Bs[k][tx * 8];
            float4 b1 = *(const float4*)&Bs[k][tx * 8 + 4];
            u64 rb2[4] = { pk2(b0.x, b0.y), pk2(b0.z, b0.w),
                           pk2(b1.x, b1.y), pk2(b1.z, b1.w) };
            float ra[8] = { a0.x, a0.y, a0.z, a0.w, a1.x, a1.y, a1.z, a1.w };
#pragma unroll
            for (int i = 0; i < 8; i++) {
                u64 ai = pk2(ra[i], ra[i]);
#pragma unroll
                for (int j = 0; j < 4; j++) ffma2(acc2[i][j], ai, rb2[j]);
            }
        }
        __syncthreads();
    }
#pragma unroll
    for (int i = 0; i < 8; i++) {
        float* crow = C + (size_t)(bm + ty * 8 + i) * N + bn + tx * 8;
#pragma unroll
        for (int j4 = 0; j4 < 2; j4++) {
            float4 v;
            upk2(acc2[i][j4 * 2 + 0], v.x, v.y);
            upk2(acc2[i][j4 * 2 + 1], v.z, v.w);
            if (ADD_BIAS) {
                v.x += bias[bn + tx * 8 + j4 * 4 + 0];
                v.y += bias[bn + tx * 8 + j4 * 4 + 1];
                v.z += bias[bn + tx * 8 + j4 * 4 + 2];
                v.w += bias[bn + tx * 8 + j4 * 4 + 3];
            }
            *(float4*)(crow + j4 * 4) = v;
        }
    }
}

// ---------------- K4: fused flash attention with additive bias -------------
// Block = (qtile, head, batch), 128 threads: thread t -> query row (t&63),
// V-half (t>>6). Scores computed cooperatively into smem (no redundant QK).
__global__ __launch_bounds__(128) void flash_attn_kernel() {
    __shared__ __align__(16) float Ks[CK_][QK_];    //  6.3 KB
    __shared__ __align__(16) float Vs[CK_][VD_];    // 25.1 KB
    __shared__ __align__(16) float Ss[QT_][CK_];    // 12.5 KB (stride 49 odd -> conflict-free)
    int t = threadIdx.x;
    int half = t >> 6;
    int r = t & 63;
    int b = blockIdx.z, h = blockIdx.y;
    int qrow = blockIdx.x * QT_ + r;
    bool valid = qrow < L_;
    const float scale = 0.17677669529663687f;   // 32^-0.5

    u64 q2[16];
    if (valid) {
        const float4* qp = (const float4*)(g_qkv + (size_t)(b * L_ + qrow) * QKVN_ + h * EH_);
#pragma unroll
        for (int i = 0; i < 8; i++) {
            float4 v = qp[i];
            q2[i * 2 + 0] = pk2(v.x, v.y);
            q2[i * 2 + 1] = pk2(v.z, v.w);
        }
    }
    u64 acc2[32];
#pragma unroll
    for (int i = 0; i < 32; i++) acc2[i] = 0ull;
    float m = -1e30f, l = 0.f;

    for (int kc = 0; kc < L_ / CK_; kc++) {
        int j0 = kc * CK_;
        // cooperative loads: K chunk (49x32) and V chunk (49x128), float4
        for (int i = t; i < CK_ * QK_ / 4; i += 128) {
            int jj = i >> 3; int cc = (i & 7) << 2;
            *(float4*)&Ks[jj][cc] =
                *(const float4*)(g_qkv + (size_t)(b * L_ + j0 + jj) * QKVN_ + h * EH_ + QK_ + cc);
        }
        for (int i = t; i < CK_ * VD_ / 4; i += 128) {
            int jj = i >> 5; int cc = (i & 31) << 2;
            *(float4*)&Vs[jj][cc] =
                *(const float4*)(g_qkv + (size_t)(b * L_ + j0 + jj) * QKVN_ + h * EH_ + 2 * QK_ + cc);
        }
        __syncthreads();

        // scores: thread (r, half) computes its row's keys with parity == half
        if (valid) {
            const float* brow = g_bias + ((size_t)h * L_ + qrow) * L_ + j0;
            for (int j = half; j < CK_; j += 2) {
                u64 dd = 0ull;
                const ulonglong2* kr = (const ulonglong2*)&Ks[j][0];
#pragma unroll
                for (int c2 = 0; c2 < 8; c2++) {
                    ulonglong2 kk = kr[c2];
                    ffma2(dd, q2[c2 * 2 + 0], kk.x);
                    ffma2(dd, q2[c2 * 2 + 1], kk.y);
                }
                float lo, hi; upk2(dd, lo, hi);
                Ss[r][j] = fmaf(lo + hi, scale, __ldg(brow + j));
            }
        }
        __syncthreads();

        // online softmax + PV accumulate (each thread: full row stats, half of V dims)
        if (valid) {
            float mc = -1e30f;
#pragma unroll
            for (int j = 0; j < CK_; j++) mc = fmaxf(mc, Ss[r][j]);
            float mnew = fmaxf(m, mc);
            float corr = __expf(m - mnew);
            l *= corr;
            u64 cc2 = pk2(corr, corr);
#pragma unroll
            for (int i = 0; i < 32; i++) fmul2(acc2[i], cc2);
#pragma unroll 1
            for (int j = 0; j < CK_; j++) {
                float p = __expf(Ss[r][j] - mnew);
                l += p;
                u64 pp = pk2(p, p);
                const ulonglong2* vr = (const ulonglong2*)&Vs[j][half * 64];
#pragma unroll
                for (int d4 = 0; d4 < 16; d4++) {
                    ulonglong2 v = vr[d4];
                    ffma2(acc2[d4 * 2 + 0], pp, v.x);
                    ffma2(acc2[d4 * 2 + 1], pp, v.y);
                }
            }
            m = mnew;
        }
        __syncthreads();
    }

    if (valid) {
        float inv = 1.0f / l;
        u64 iv2 = pk2(inv, inv);
        float* op = g_ao + (size_t)(b * L_ + qrow) * (H_ * VD_) + h * VD_ + half * 64;
#pragma unroll
        for (int d4 = 0; d4 < 16; d4++) {
            u64 x0 = acc2[d4 * 2 + 0], x1 = acc2[d4 * 2 + 1];
            fmul2(x0, iv2); fmul2(x1, iv2);
            float4 v;
            upk2(x0, v.x, v.y);
            upk2(x1, v.z, v.w);
            *(float4*)(op + d4 * 4) = v;
        }
    }
}

// ---------------- launch ---------------------------------------------------
extern "C" void kernel_launch(void* const* d_in, const int* in_sizes, int n_in,
                              void* d_out, int out_size) {
    const float* x         = (const float*)d_in[0];   // (16,784,384)
    const float* Wqkv      = (const float*)d_in[1];   // (1536,384)
    const float* Wproj     = (const float*)d_in[2];   // (384,1024)
    const float* bproj     = (const float*)d_in[3];   // (384,)
    const float* ab_table  = (const float*)d_in[4];   // (8,625)
    const int*   bias_idxs = (const int*)d_in[5];     // (625,625)
    float* out = (float*)d_out;

    void* pqkv = nullptr; cudaGetSymbolAddress(&pqkv, g_qkv);
    void* pao  = nullptr; cudaGetSymbolAddress(&pao,  g_ao);

    build_interp_kernel<<<1, 1024>>>();

    const int totAb = H_ * RESI_ * RESI_;
    gather_ab_kernel<<<(totAb + 255) / 256, 256>>>(ab_table, bias_idxs);

    build_bias_kernel<<<(H_ * L_ * L_) / 256, 256>>>();   // 4917248 / 256 exact

    dim3 gqkv(QKVN_ / 128, (B_ * L_) / 128);
    sgemm_nt_kernel<false><<<gqkv, 256>>>(x, Wqkv, nullptr, (float*)pqkv,
                                          B_ * L_, QKVN_, D_);

    dim3 gatt((L_ + QT_ - 1) / QT_, H_, B_);
    flash_attn_kernel<<<gatt, 128>>>();

    dim3 gproj(D_ / 128, (B_ * L_) / 128);
    sgemm_nt_kernel<true><<<gproj, 256>>>((const float*)pao, Wproj, bproj, out,
                                          B_ * L_, D_, H_ * VD_);
}

// round 4
// speedup vs baseline: 1.2245x; 1.1640x over previous
#include <cuda_runtime.h>
#include <cuda_bf16.h>
#include <math.h>
#include <cstdint>

#define B_     16
#define L_     784
#define D_     384
#define H_     8
#define QK_    32
#define VD_    128
#define EH_    192          // per-head qkv width
#define QKVN_  1536
#define RESI_  625
#define CK_    49           // keys per flash chunk (784 = 16*49)
#define QT_    64           // queries per flash block

typedef unsigned long long u64;

// ---------------- packed fp32x2 helpers (sm_103a) ---------------------------
__device__ __forceinline__ u64 pk2(float a, float b) {
    u64 r; asm("mov.b64 %0, {%1, %2};" : "=l"(r) : "f"(a), "f"(b)); return r;
}
__device__ __forceinline__ void upk2(u64 v, float& a, float& b) {
    asm("mov.b64 {%0, %1}, %2;" : "=f"(a), "=f"(b) : "l"(v));
}
__device__ __forceinline__ void ffma2(u64& d, u64 a, u64 b) {
    asm("fma.rn.f32x2 %0, %1, %2, %0;" : "+l"(d) : "l"(a), "l"(b));
}
__device__ __forceinline__ void fmul2(u64& d, u64 a) {
    asm("mul.rn.f32x2 %0, %0, %1;" : "+l"(d) : "l"(a));
}

__device__ __forceinline__ uint32_t smem_u32(const void* p) {
    uint32_t a;
    asm("{ .reg .u64 t; cvta.to.shared.u64 t, %1; cvt.u32.u64 %0, t; }" : "=r"(a) : "l"(p));
    return a;
}

// ---------------- scratch (static device globals; no runtime alloc) --------
__device__ float g_qkv[(size_t)B_ * L_ * QKVN_];        // 77 MB
__device__ float g_abg[(size_t)H_ * RESI_ * RESI_];     // 12.5 MB
__device__ float g_bias[(size_t)H_ * L_ * L_];          // 19.7 MB
__device__ float g_ao[(size_t)B_ * L_ * H_ * VD_];      // 51 MB
__device__ float g_iw[L_ * 4];
__device__ int   g_ii[L_ * 4];

// ---------------- K0: bicubic interp weights/indices -----------------------
__global__ void build_interp_kernel() {
    int o = blockIdx.x * blockDim.x + threadIdx.x;
    if (o >= L_) return;
    const float a = -0.75f;
    float scale = (float)RESI_ / (float)L_;
    float src = ((float)o + 0.5f) * scale - 0.5f;
    float f = floorf(src);
    float t = src - f;
    float xs[4] = { t + 1.0f, t, 1.0f - t, 2.0f - t };
#pragma unroll
    for (int i = 0; i < 4; i++) {
        float ax = fabsf(xs[i]);
        float w1 = ((a + 2.0f) * ax - (a + 3.0f)) * ax * ax + 1.0f;
        float w2 = a * (((ax - 5.0f) * ax + 8.0f) * ax - 4.0f);
        float w = (ax <= 1.0f) ? w1 : ((ax < 2.0f) ? w2 : 0.0f);
        g_iw[o * 4 + i] = w;
        int id = (int)f - 1 + i;
        id = id < 0 ? 0 : (id > RESI_ - 1 ? RESI_ - 1 : id);
        g_ii[o * 4 + i] = id;
    }
}

// ---------------- K1: ab gather --------------------------------------------
__global__ void gather_ab_kernel(const float* __restrict__ ab_table,
                                 const int* __restrict__ bias_idxs) {
    int i = blockIdx.x * blockDim.x + threadIdx.x;
    const int total = H_ * RESI_ * RESI_;
    if (i >= total) return;
    int h = i / (RESI_ * RESI_);
    int ij = i - h * (RESI_ * RESI_);
    g_abg[i] = ab_table[h * RESI_ + bias_idxs[ij]];
}

// ---------------- K2: bias build -------------------------------------------
__global__ void build_bias_kernel() {
    int i = blockIdx.x * blockDim.x + threadIdx.x;
    const int total = H_ * L_ * L_;
    if (i >= total) return;
    int h = i / (L_ * L_);
    int r = i - h * (L_ * L_);
    int o = r / L_;
    int p = r - o * L_;
    const float* __restrict__ abh = g_abg + (size_t)h * RESI_ * RESI_;
    float wp[4]; int ip[4];
#pragma unroll
    for (int bb = 0; bb < 4; bb++) { wp[bb] = g_iw[p * 4 + bb]; ip[bb] = g_ii[p * 4 + bb]; }
    float s = 0.f;
#pragma unroll
    for (int aa = 0; aa < 4; aa++) {
        float wa = g_iw[o * 4 + aa];
        const float* row = abh + (size_t)g_ii[o * 4 + aa] * RESI_;
        float sb = 0.f;
#pragma unroll
        for (int bb = 0; bb < 4; bb++) sb = fmaf(wp[bb], __ldg(row + ip[bb]), sb);
        s = fmaf(wa, sb, s);
    }
    g_bias[i] = s;
}

// ---------------- mma.sync helpers -----------------------------------------
__device__ __forceinline__ void ldsm4(uint32_t& r0, uint32_t& r1, uint32_t& r2, uint32_t& r3,
                                      uint32_t addr) {
    asm volatile("ldmatrix.sync.aligned.m8n8.x4.shared.b16 {%0,%1,%2,%3}, [%4];"
                 : "=r"(r0), "=r"(r1), "=r"(r2), "=r"(r3) : "r"(addr));
}
__device__ __forceinline__ void ldsm2(uint32_t& r0, uint32_t& r1, uint32_t addr) {
    asm volatile("ldmatrix.sync.aligned.m8n8.x2.shared.b16 {%0,%1}, [%2];"
                 : "=r"(r0), "=r"(r1) : "r"(addr));
}
__device__ __forceinline__ void mma16816(float* d, const uint32_t* a, const uint32_t* b) {
    asm volatile("mma.sync.aligned.m16n8k16.row.col.f32.bf16.bf16.f32 "
                 "{%0,%1,%2,%3}, {%4,%5,%6,%7}, {%8,%9}, {%0,%1,%2,%3};"
                 : "+f"(d[0]), "+f"(d[1]), "+f"(d[2]), "+f"(d[3])
                 : "r"(a[0]), "r"(a[1]), "r"(a[2]), "r"(a[3]), "r"(b[0]), "r"(b[1]));
}
__device__ __forceinline__ uint32_t pkbf(float a, float b) {
    __nv_bfloat162 t = __floats2bfloat162_rn(a, b);
    return *reinterpret_cast<uint32_t*>(&t);
}

// ---------------- K3/K5: mma.sync bf16-split GEMM: C = A @ W^T (+bias) -----
// A [M,K] f32 row-major, W [N,K] f32 row-major. CTA tile 128x128, BK=32.
// 8 warps = 2(M) x 4(N); warp tile 64x32. 3-term split for fp32 accuracy.
#define GS 40   // smem row stride (bf16 elems), odd*8 -> conflict-free ldmatrix
template <bool ADD_BIAS>
__global__ __launch_bounds__(256) void mma_gemm_nt(
    const float* __restrict__ A, const float* __restrict__ W,
    const float* __restrict__ bias, float* __restrict__ C,
    int M, int N, int K)
{
    __shared__ __align__(16) __nv_bfloat16 Ah[128][GS];
    __shared__ __align__(16) __nv_bfloat16 Al[128][GS];
    __shared__ __align__(16) __nv_bfloat16 Bh[128][GS];
    __shared__ __align__(16) __nv_bfloat16 Bl[128][GS];

    const int tid = threadIdx.x;
    const int wid = tid >> 5;
    const int lane = tid & 31;
    const int wm = wid >> 2;          // 0..1
    const int wn = wid & 3;           // 0..3
    const int bm = blockIdx.y * 128;
    const int bn = blockIdx.x * 128;

    float acc[4][4][4];
#pragma unroll
    for (int i = 0; i < 4; i++)
#pragma unroll
        for (int j = 0; j < 4; j++)
#pragma unroll
            for (int e = 0; e < 4; e++) acc[i][j][e] = 0.f;

    const int q = lane >> 3;          // 0..3
    const int rr = lane & 7;          // 0..7

    for (int k0 = 0; k0 < K; k0 += 32) {
        // ---- load + split: 128 rows x 32 cols each of A and W ----
#pragma unroll
        for (int it = 0; it < 4; it++) {
            int idx = tid + it * 256;     // 0..1023
            int row = idx >> 3;
            int c4 = (idx & 7) << 2;      // 0,4,...,28
            {
                float4 v = *(const float4*)(A + (size_t)(bm + row) * K + k0 + c4);
                __nv_bfloat162 h01 = __floats2bfloat162_rn(v.x, v.y);
                __nv_bfloat162 h23 = __floats2bfloat162_rn(v.z, v.w);
                float l0 = v.x - __bfloat162float(h01.x), l1 = v.y - __bfloat162float(h01.y);
                float l2 = v.z - __bfloat162float(h23.x), l3 = v.w - __bfloat162float(h23.y);
                *(uint2*)&Ah[row][c4] = make_uint2(*(uint32_t*)&h01, *(uint32_t*)&h23);
                *(uint2*)&Al[row][c4] = make_uint2(pkbf(l0, l1), pkbf(l2, l3));
            }
            {
                float4 v = *(const float4*)(W + (size_t)(bn + row) * K + k0 + c4);
                __nv_bfloat162 h01 = __floats2bfloat162_rn(v.x, v.y);
                __nv_bfloat162 h23 = __floats2bfloat162_rn(v.z, v.w);
                float l0 = v.x - __bfloat162float(h01.x), l1 = v.y - __bfloat162float(h01.y);
                float l2 = v.z - __bfloat162float(h23.x), l3 = v.w - __bfloat162float(h23.y);
                *(uint2*)&Bh[row][c4] = make_uint2(*(uint32_t*)&h01, *(uint32_t*)&h23);
                *(uint2*)&Bl[row][c4] = make_uint2(pkbf(l0, l1), pkbf(l2, l3));
            }
        }
        __syncthreads();

        // ---- two k16 steps of mma ----
#pragma unroll
        for (int ks = 0; ks < 2; ks++) {
            int kc = ks * 16;
            uint32_t ah[4][4], al[4][4];
#pragma unroll
            for (int i = 0; i < 4; i++) {
                int arow = wm * 64 + i * 16 + (q & 1) * 8 + rr;
                int acol = kc + (q >> 1) * 8;
                ldsm4(ah[i][0], ah[i][1], ah[i][2], ah[i][3], smem_u32(&Ah[arow][acol]));
                ldsm4(al[i][0], al[i][1], al[i][2], al[i][3], smem_u32(&Al[arow][acol]));
            }
            uint32_t bh[4][2], bl[4][2];
#pragma unroll
            for (int j = 0; j < 4; j++) {
                int brow = wn * 32 + j * 8 + rr;
                int bcol = kc + (q & 1) * 8;
                ldsm2(bh[j][0], bh[j][1], smem_u32(&Bh[brow][bcol]));
                ldsm2(bl[j][0], bl[j][1], smem_u32(&Bl[brow][bcol]));
            }
#pragma unroll
            for (int i = 0; i < 4; i++)
#pragma unroll
                for (int j = 0; j < 4; j++) {
                    mma16816(acc[i][j], ah[i], bh[j]);
                    mma16816(acc[i][j], ah[i], bl[j]);
                    mma16816(acc[i][j], al[i], bh[j]);
                }
        }
        __syncthreads();
    }

    // ---- epilogue ----
    const int gid = lane >> 2;       // 0..7
    const int tig = lane & 3;        // 0..3
#pragma unroll
    for (int i = 0; i < 4; i++) {
#pragma unroll
        for (int j = 0; j < 4; j++) {
            int row0 = bm + wm * 64 + i * 16 + gid;
            int col = bn + wn * 32 + j * 8 + tig * 2;
            float2 v0 = make_float2(acc[i][j][0], acc[i][j][1]);
            float2 v1 = make_float2(acc[i][j][2], acc[i][j][3]);
            if (ADD_BIAS) {
                v0.x += bias[col]; v0.y += bias[col + 1];
                v1.x += bias[col]; v1.y += bias[col + 1];
            }
            *(float2*)(C + (size_t)row0 * N + col) = v0;
            *(float2*)(C + (size_t)(row0 + 8) * N + col) = v1;
        }
    }
}

// ---------------- K4: fused flash attention with additive bias -------------
__global__ __launch_bounds__(128) void flash_attn_kernel() {
    __shared__ __align__(16) float Ks[CK_][QK_];
    __shared__ __align__(16) float Vs[CK_][VD_];
    __shared__ __align__(16) float Ss[QT_][CK_];
    int t = threadIdx.x;
    int half = t >> 6;
    int r = t & 63;
    int b = blockIdx.z, h = blockIdx.y;
    int qrow = blockIdx.x * QT_ + r;
    bool valid = qrow < L_;
    const float scale = 0.17677669529663687f;   // 32^-0.5

    u64 q2[16];
    if (valid) {
        const float4* qp = (const float4*)(g_qkv + (size_t)(b * L_ + qrow) * QKVN_ + h * EH_);
#pragma unroll
        for (int i = 0; i < 8; i++) {
            float4 v = qp[i];
            q2[i * 2 + 0] = pk2(v.x, v.y);
            q2[i * 2 + 1] = pk2(v.z, v.w);
        }
    }
    u64 acc2[32];
#pragma unroll
    for (int i = 0; i < 32; i++) acc2[i] = 0ull;
    float m = -1e30f, l = 0.f;

    for (int kc = 0; kc < L_ / CK_; kc++) {
        int j0 = kc * CK_;
        for (int i = t; i < CK_ * QK_ / 4; i += 128) {
            int jj = i >> 3; int cc = (i & 7) << 2;
            *(float4*)&Ks[jj][cc] =
                *(const float4*)(g_qkv + (size_t)(b * L_ + j0 + jj) * QKVN_ + h * EH_ + QK_ + cc);
        }
        for (int i = t; i < CK_ * VD_ / 4; i += 128) {
            int jj = i >> 5; int cc = (i & 31) << 2;
            *(float4*)&Vs[jj][cc] =
                *(const float4*)(g_qkv + (size_t)(b * L_ + j0 + jj) * QKVN_ + h * EH_ + 2 * QK_ + cc);
        }
        __syncthreads();

        if (valid) {
            const float* brow = g_bias + ((size_t)h * L_ + qrow) * L_ + j0;
            for (int j = half; j < CK_; j += 2) {
                u64 dd = 0ull;
                const ulonglong2* kr = (const ulonglong2*)&Ks[j][0];
#pragma unroll
                for (int c2 = 0; c2 < 8; c2++) {
                    ulonglong2 kk = kr[c2];
                    ffma2(dd, q2[c2 * 2 + 0], kk.x);
                    ffma2(dd, q2[c2 * 2 + 1], kk.y);
                }
                float lo, hi; upk2(dd, lo, hi);
                Ss[r][j] = fmaf(lo + hi, scale, __ldg(brow + j));
            }
        }
        __syncthreads();

        if (valid) {
            float mc = -1e30f;
#pragma unroll
            for (int j = 0; j < CK_; j++) mc = fmaxf(mc, Ss[r][j]);
            float mnew = fmaxf(m, mc);
            float corr = __expf(m - mnew);
            l *= corr;
            u64 cc2 = pk2(corr, corr);
#pragma unroll
            for (int i = 0; i < 32; i++) fmul2(acc2[i], cc2);
#pragma unroll 1
            for (int j = 0; j < CK_; j++) {
                float p = __expf(Ss[r][j] - mnew);
                l += p;
                u64 pp = pk2(p, p);
                const ulonglong2* vr = (const ulonglong2*)&Vs[j][half * 64];
#pragma unroll
                for (int d4 = 0; d4 < 16; d4++) {
                    ulonglong2 v = vr[d4];
                    ffma2(acc2[d4 * 2 + 0], pp, v.x);
                    ffma2(acc2[d4 * 2 + 1], pp, v.y);
                }
            }
            m = mnew;
        }
        __syncthreads();
    }

    if (valid) {
        float inv = 1.0f / l;
        u64 iv2 = pk2(inv, inv);
        float* op = g_ao + (size_t)(b * L_ + qrow) * (H_ * VD_) + h * VD_ + half * 64;
#pragma unroll
        for (int d4 = 0; d4 < 16; d4++) {
            u64 x0 = acc2[d4 * 2 + 0], x1 = acc2[d4 * 2 + 1];
            fmul2(x0, iv2); fmul2(x1, iv2);
            float4 v;
            upk2(x0, v.x, v.y);
            upk2(x1, v.z, v.w);
            *(float4*)(op + d4 * 4) = v;
        }
    }
}

// ---------------- launch ---------------------------------------------------
extern "C" void kernel_launch(void* const* d_in, const int* in_sizes, int n_in,
                              void* d_out, int out_size) {
    const float* x         = (const float*)d_in[0];   // (16,784,384)
    const float* Wqkv      = (const float*)d_in[1];   // (1536,384)
    const float* Wproj     = (const float*)d_in[2];   // (384,1024)
    const float* bproj     = (const float*)d_in[3];   // (384,)
    const float* ab_table  = (const float*)d_in[4];   // (8,625)
    const int*   bias_idxs = (const int*)d_in[5];     // (625,625)
    float* out = (float*)d_out;

    void* pqkv = nullptr; cudaGetSymbolAddress(&pqkv, g_qkv);
    void* pao  = nullptr; cudaGetSymbolAddress(&pao,  g_ao);

    build_interp_kernel<<<1, 1024>>>();

    const int totAb = H_ * RESI_ * RESI_;
    gather_ab_kernel<<<(totAb + 255) / 256, 256>>>(ab_table, bias_idxs);

    build_bias_kernel<<<(H_ * L_ * L_) / 256, 256>>>();

    dim3 gqkv(QKVN_ / 128, (B_ * L_) / 128);
    mma_gemm_nt<false><<<gqkv, 256>>>(x, Wqkv, nullptr, (float*)pqkv,
                                      B_ * L_, QKVN_, D_);

    dim3 gatt((L_ + QT_ - 1) / QT_, H_, B_);
    flash_attn_kernel<<<gatt, 128>>>();

    dim3 gproj(D_ / 128, (B_ * L_) / 128);
    mma_gemm_nt<true><<<gproj, 256>>>((const float*)pao, Wproj, bproj, out,
                                      B_ * L_, D_, H_ * VD_);
}

// round 5
// speedup vs baseline: 2.6003x; 2.1236x over previous
#include <cuda_runtime.h>
#include <cuda_bf16.h>
#include <math.h>
#include <cstdint>

#define B_     16
#define L_     784
#define D_     384
#define H_     8
#define QK_    32
#define VD_    128
#define EH_    192          // per-head qkv width
#define QKVN_  1536
#define RESI_  625

#define FQT 112             // q rows per CTA (784 = 7*112)
#define FCK 112             // keys per chunk
#define VSTR 136            // V smem stride in bf16 (conflict-free trans ldsm)
#define KSTR 40             // K/Q smem stride in bf16

// ---------------- scratch (static device globals; no runtime alloc) --------
__device__ float g_qkv[(size_t)B_ * L_ * QKVN_];        // 77 MB
__device__ float g_abg[(size_t)H_ * RESI_ * RESI_];     // 12.5 MB
__device__ float g_bias[(size_t)H_ * L_ * L_];          // 19.7 MB
__device__ float g_ao[(size_t)B_ * L_ * H_ * VD_];      // 51 MB
__device__ float g_iw[L_ * 4];
__device__ int   g_ii[L_ * 4];

__device__ __forceinline__ uint32_t smem_u32(const void* p) {
    uint32_t a;
    asm("{ .reg .u64 t; cvta.to.shared.u64 t, %1; cvt.u32.u64 %0, t; }" : "=r"(a) : "l"(p));
    return a;
}

// ---------------- K0: bicubic interp weights/indices -----------------------
__global__ void build_interp_kernel() {
    int o = blockIdx.x * blockDim.x + threadIdx.x;
    if (o >= L_) return;
    const float a = -0.75f;
    float scale = (float)RESI_ / (float)L_;
    float src = ((float)o + 0.5f) * scale - 0.5f;
    float f = floorf(src);
    float t = src - f;
    float xs[4] = { t + 1.0f, t, 1.0f - t, 2.0f - t };
#pragma unroll
    for (int i = 0; i < 4; i++) {
        float ax = fabsf(xs[i]);
        float w1 = ((a + 2.0f) * ax - (a + 3.0f)) * ax * ax + 1.0f;
        float w2 = a * (((ax - 5.0f) * ax + 8.0f) * ax - 4.0f);
        float w = (ax <= 1.0f) ? w1 : ((ax < 2.0f) ? w2 : 0.0f);
        g_iw[o * 4 + i] = w;
        int id = (int)f - 1 + i;
        id = id < 0 ? 0 : (id > RESI_ - 1 ? RESI_ - 1 : id);
        g_ii[o * 4 + i] = id;
    }
}

// ---------------- K1: ab gather --------------------------------------------
__global__ void gather_ab_kernel(const float* __restrict__ ab_table,
                                 const int* __restrict__ bias_idxs) {
    int i = blockIdx.x * blockDim.x + threadIdx.x;
    const int total = H_ * RESI_ * RESI_;
    if (i >= total) return;
    int h = i / (RESI_ * RESI_);
    int ij = i - h * (RESI_ * RESI_);
    g_abg[i] = ab_table[h * RESI_ + bias_idxs[ij]];
}

// ---------------- K2: bias build -------------------------------------------
__global__ void build_bias_kernel() {
    int i = blockIdx.x * blockDim.x + threadIdx.x;
    const int total = H_ * L_ * L_;
    if (i >= total) return;
    int h = i / (L_ * L_);
    int r = i - h * (L_ * L_);
    int o = r / L_;
    int p = r - o * L_;
    const float* __restrict__ abh = g_abg + (size_t)h * RESI_ * RESI_;
    float wp[4]; int ip[4];
#pragma unroll
    for (int bb = 0; bb < 4; bb++) { wp[bb] = g_iw[p * 4 + bb]; ip[bb] = g_ii[p * 4 + bb]; }
    float s = 0.f;
#pragma unroll
    for (int aa = 0; aa < 4; aa++) {
        float wa = g_iw[o * 4 + aa];
        const float* row = abh + (size_t)g_ii[o * 4 + aa] * RESI_;
        float sb = 0.f;
#pragma unroll
        for (int bb = 0; bb < 4; bb++) sb = fmaf(wp[bb], __ldg(row + ip[bb]), sb);
        s = fmaf(wa, sb, s);
    }
    g_bias[i] = s;
}

// ---------------- mma.sync helpers -----------------------------------------
__device__ __forceinline__ void ldsm4(uint32_t& r0, uint32_t& r1, uint32_t& r2, uint32_t& r3,
                                      uint32_t addr) {
    asm volatile("ldmatrix.sync.aligned.m8n8.x4.shared.b16 {%0,%1,%2,%3}, [%4];"
                 : "=r"(r0), "=r"(r1), "=r"(r2), "=r"(r3) : "r"(addr));
}
__device__ __forceinline__ void ldsm2(uint32_t& r0, uint32_t& r1, uint32_t addr) {
    asm volatile("ldmatrix.sync.aligned.m8n8.x2.shared.b16 {%0,%1}, [%2];"
                 : "=r"(r0), "=r"(r1) : "r"(addr));
}
__device__ __forceinline__ void ldsm2t(uint32_t& r0, uint32_t& r1, uint32_t addr) {
    asm volatile("ldmatrix.sync.aligned.m8n8.x2.trans.shared.b16 {%0,%1}, [%2];"
                 : "=r"(r0), "=r"(r1) : "r"(addr));
}
__device__ __forceinline__ void mma16816(float* d, const uint32_t* a, const uint32_t* b) {
    asm volatile("mma.sync.aligned.m16n8k16.row.col.f32.bf16.bf16.f32 "
                 "{%0,%1,%2,%3}, {%4,%5,%6,%7}, {%8,%9}, {%0,%1,%2,%3};"
                 : "+f"(d[0]), "+f"(d[1]), "+f"(d[2]), "+f"(d[3])
                 : "r"(a[0]), "r"(a[1]), "r"(a[2]), "r"(a[3]), "r"(b[0]), "r"(b[1]));
}
__device__ __forceinline__ uint32_t pkbf(float a, float b) {
    __nv_bfloat162 t = __floats2bfloat162_rn(a, b);
    return *reinterpret_cast<uint32_t*>(&t);
}

// ---------------- K3/K5: mma.sync bf16-split GEMM: C = A @ W^T (+bias) -----
#define GS 40
template <bool ADD_BIAS>
__global__ __launch_bounds__(256) void mma_gemm_nt(
    const float* __restrict__ A, const float* __restrict__ W,
    const float* __restrict__ bias, float* __restrict__ C,
    int M, int N, int K)
{
    __shared__ __align__(16) __nv_bfloat16 Ah[128][GS];
    __shared__ __align__(16) __nv_bfloat16 Al[128][GS];
    __shared__ __align__(16) __nv_bfloat16 Bh[128][GS];
    __shared__ __align__(16) __nv_bfloat16 Bl[128][GS];

    const int tid = threadIdx.x;
    const int wid = tid >> 5;
    const int lane = tid & 31;
    const int wm = wid >> 2;
    const int wn = wid & 3;
    const int bm = blockIdx.y * 128;
    const int bn = blockIdx.x * 128;

    float acc[4][4][4];
#pragma unroll
    for (int i = 0; i < 4; i++)
#pragma unroll
        for (int j = 0; j < 4; j++)
#pragma unroll
            for (int e = 0; e < 4; e++) acc[i][j][e] = 0.f;

    const int q = lane >> 3;
    const int rr = lane & 7;

    for (int k0 = 0; k0 < K; k0 += 32) {
#pragma unroll
        for (int it = 0; it < 4; it++) {
            int idx = tid + it * 256;
            int row = idx >> 3;
            int c4 = (idx & 7) << 2;
            {
                float4 v = *(const float4*)(A + (size_t)(bm + row) * K + k0 + c4);
                __nv_bfloat162 h01 = __floats2bfloat162_rn(v.x, v.y);
                __nv_bfloat162 h23 = __floats2bfloat162_rn(v.z, v.w);
                float l0 = v.x - __bfloat162float(h01.x), l1 = v.y - __bfloat162float(h01.y);
                float l2 = v.z - __bfloat162float(h23.x), l3 = v.w - __bfloat162float(h23.y);
                *(uint2*)&Ah[row][c4] = make_uint2(*(uint32_t*)&h01, *(uint32_t*)&h23);
                *(uint2*)&Al[row][c4] = make_uint2(pkbf(l0, l1), pkbf(l2, l3));
            }
            {
                float4 v = *(const float4*)(W + (size_t)(bn + row) * K + k0 + c4);
                __nv_bfloat162 h01 = __floats2bfloat162_rn(v.x, v.y);
                __nv_bfloat162 h23 = __floats2bfloat162_rn(v.z, v.w);
                float l0 = v.x - __bfloat162float(h01.x), l1 = v.y - __bfloat162float(h01.y);
                float l2 = v.z - __bfloat162float(h23.x), l3 = v.w - __bfloat162float(h23.y);
                *(uint2*)&Bh[row][c4] = make_uint2(*(uint32_t*)&h01, *(uint32_t*)&h23);
                *(uint2*)&Bl[row][c4] = make_uint2(pkbf(l0, l1), pkbf(l2, l3));
            }
        }
        __syncthreads();

#pragma unroll
        for (int ks = 0; ks < 2; ks++) {
            int kc = ks * 16;
            uint32_t ah[4][4], al[4][4];
#pragma unroll
            for (int i = 0; i < 4; i++) {
                int arow = wm * 64 + i * 16 + (q & 1) * 8 + rr;
                int acol = kc + (q >> 1) * 8;
                ldsm4(ah[i][0], ah[i][1], ah[i][2], ah[i][3], smem_u32(&Ah[arow][acol]));
                ldsm4(al[i][0], al[i][1], al[i][2], al[i][3], smem_u32(&Al[arow][acol]));
            }
            uint32_t bh[4][2], bl[4][2];
#pragma unroll
            for (int j = 0; j < 4; j++) {
                int brow = wn * 32 + j * 8 + rr;
                int bcol = kc + (q & 1) * 8;
                ldsm2(bh[j][0], bh[j][1], smem_u32(&Bh[brow][bcol]));
                ldsm2(bl[j][0], bl[j][1], smem_u32(&Bl[brow][bcol]));
            }
#pragma unroll
            for (int i = 0; i < 4; i++)
#pragma unroll
                for (int j = 0; j < 4; j++) {
                    mma16816(acc[i][j], ah[i], bh[j]);
                    mma16816(acc[i][j], ah[i], bl[j]);
                    mma16816(acc[i][j], al[i], bh[j]);
                }
        }
        __syncthreads();
    }

    const int gid = lane >> 2;
    const int tig = lane & 3;
#pragma unroll
    for (int i = 0; i < 4; i++) {
#pragma unroll
        for (int j = 0; j < 4; j++) {
            int row0 = bm + wm * 64 + i * 16 + gid;
            int col = bn + wn * 32 + j * 8 + tig * 2;
            float2 v0 = make_float2(acc[i][j][0], acc[i][j][1]);
            float2 v1 = make_float2(acc[i][j][2], acc[i][j][3]);
            if (ADD_BIAS) {
                v0.x += bias[col]; v0.y += bias[col + 1];
                v1.x += bias[col]; v1.y += bias[col + 1];
            }
            *(float2*)(C + (size_t)row0 * N + col) = v0;
            *(float2*)(C + (size_t)(row0 + 8) * N + col) = v1;
        }
    }
}

// ---------------- K4: tensor-core flash attention --------------------------
// grid (7, H, B), 224 threads = 7 warps x 16 q-rows. 784 = 7*112 exact.
struct FlashSmem {
    __nv_bfloat16 Kh[FQT][KSTR];
    __nv_bfloat16 Kl[FQT][KSTR];
    __nv_bfloat16 Vh[FCK][VSTR];
    __nv_bfloat16 Vl[FCK][VSTR];
};

__global__ __launch_bounds__(224) void flash_mma_kernel() {
    extern __shared__ __align__(16) char smraw[];
    FlashSmem& SM = *reinterpret_cast<FlashSmem*>(smraw);
    const int tid = threadIdx.x;
    const int warp = tid >> 5, lane = tid & 31;
    const int b = blockIdx.z, h = blockIdx.y, qb = blockIdx.x;
    const int q8 = lane >> 3, rr = lane & 7;
    const int gid = lane >> 2, tig = lane & 3;
    const float scale = 0.17677669529663687f;

    // ---- stage Q tile (112x32) split into Kh/Kl buffers ----
    {
        const float* Qg = g_qkv + (size_t)(b * L_ + qb * FQT) * QKVN_ + h * EH_;
#pragma unroll
        for (int it = 0; it < 4; it++) {
            int idx = tid + it * 224;
            int row = idx >> 3, c4 = (idx & 7) << 2;
            float4 v = *(const float4*)(Qg + (size_t)row * QKVN_ + c4);
            __nv_bfloat162 h01 = __floats2bfloat162_rn(v.x, v.y);
            __nv_bfloat162 h23 = __floats2bfloat162_rn(v.z, v.w);
            float l0 = v.x - __bfloat162float(h01.x), l1 = v.y - __bfloat162float(h01.y);
            float l2 = v.z - __bfloat162float(h23.x), l3 = v.w - __bfloat162float(h23.y);
            *(uint2*)&SM.Kh[row][c4] = make_uint2(*(uint32_t*)&h01, *(uint32_t*)&h23);
            *(uint2*)&SM.Kl[row][c4] = make_uint2(pkbf(l0, l1), pkbf(l2, l3));
        }
    }
    __syncthreads();
    uint32_t qhf[2][4], qlf[2][4];
#pragma unroll
    for (int s = 0; s < 2; s++) {
        int arow = warp * 16 + (q8 & 1) * 8 + rr;
        int acol = s * 16 + (q8 >> 1) * 8;
        ldsm4(qhf[s][0], qhf[s][1], qhf[s][2], qhf[s][3], smem_u32(&SM.Kh[arow][acol]));
        ldsm4(qlf[s][0], qlf[s][1], qlf[s][2], qlf[s][3], smem_u32(&SM.Kl[arow][acol]));
    }

    float out[16][4];
#pragma unroll
    for (int j = 0; j < 16; j++)
#pragma unroll
        for (int e = 0; e < 4; e++) out[j][e] = 0.f;
    float m0 = -1e30f, m1 = -1e30f, l0s = 0.f, l1s = 0.f;

    const int r0 = qb * FQT + warp * 16 + gid;
    const float* biasbase = g_bias + ((size_t)h * L_ + r0) * L_;

    for (int kc = 0; kc < 7; kc++) {
        int j0 = kc * FCK;
        __syncthreads();
        // ---- load K chunk (112x32) split ----
        {
            const float* Kg = g_qkv + (size_t)(b * L_ + j0) * QKVN_ + h * EH_ + QK_;
#pragma unroll
            for (int it = 0; it < 4; it++) {
                int idx = tid + it * 224;
                int row = idx >> 3, c4 = (idx & 7) << 2;
                float4 v = *(const float4*)(Kg + (size_t)row * QKVN_ + c4);
                __nv_bfloat162 h01 = __floats2bfloat162_rn(v.x, v.y);
                __nv_bfloat162 h23 = __floats2bfloat162_rn(v.z, v.w);
                float l0 = v.x - __bfloat162float(h01.x), l1 = v.y - __bfloat162float(h01.y);
                float l2 = v.z - __bfloat162float(h23.x), l3 = v.w - __bfloat162float(h23.y);
                *(uint2*)&SM.Kh[row][c4] = make_uint2(*(uint32_t*)&h01, *(uint32_t*)&h23);
                *(uint2*)&SM.Kl[row][c4] = make_uint2(pkbf(l0, l1), pkbf(l2, l3));
            }
        }
        // ---- load V chunk (112x128) split ----
        {
            const float* Vg = g_qkv + (size_t)(b * L_ + j0) * QKVN_ + h * EH_ + 2 * QK_;
#pragma unroll
            for (int it = 0; it < 16; it++) {
                int idx = tid + it * 224;
                int row = idx >> 5, c4 = (idx & 31) << 2;
                float4 v = *(const float4*)(Vg + (size_t)row * QKVN_ + c4);
                __nv_bfloat162 h01 = __floats2bfloat162_rn(v.x, v.y);
                __nv_bfloat162 h23 = __floats2bfloat162_rn(v.z, v.w);
                float l0 = v.x - __bfloat162float(h01.x), l1 = v.y - __bfloat162float(h01.y);
                float l2 = v.z - __bfloat162float(h23.x), l3 = v.w - __bfloat162float(h23.y);
                *(uint2*)&SM.Vh[row][c4] = make_uint2(*(uint32_t*)&h01, *(uint32_t*)&h23);
                *(uint2*)&SM.Vl[row][c4] = make_uint2(pkbf(l0, l1), pkbf(l2, l3));
            }
        }
        __syncthreads();

        // ---- S = Q K^T (3-term split) ----
        float sa[14][4];
#pragma unroll
        for (int t = 0; t < 14; t++)
#pragma unroll
            for (int e = 0; e < 4; e++) sa[t][e] = 0.f;
#pragma unroll
        for (int s = 0; s < 2; s++) {
#pragma unroll
            for (int t = 0; t < 14; t++) {
                uint32_t bh[2], bl[2];
                int brow = t * 8 + rr;
                int bcol = s * 16 + (q8 & 1) * 8;
                ldsm2(bh[0], bh[1], smem_u32(&SM.Kh[brow][bcol]));
                ldsm2(bl[0], bl[1], smem_u32(&SM.Kl[brow][bcol]));
                mma16816(sa[t], qhf[s], bh);
                mma16816(sa[t], qhf[s], bl);
                mma16816(sa[t], qlf[s], bh);
            }
        }

        // ---- bias + scale + row max ----
        float ml0 = -1e30f, ml1 = -1e30f;
#pragma unroll
        for (int t = 0; t < 14; t++) {
            int col = j0 + t * 8 + tig * 2;
            float2 b0 = *(const float2*)(biasbase + col);
            float2 b1 = *(const float2*)(biasbase + (size_t)8 * L_ + col);
            sa[t][0] = fmaf(sa[t][0], scale, b0.x);
            sa[t][1] = fmaf(sa[t][1], scale, b0.y);
            sa[t][2] = fmaf(sa[t][2], scale, b1.x);
            sa[t][3] = fmaf(sa[t][3], scale, b1.y);
            ml0 = fmaxf(ml0, fmaxf(sa[t][0], sa[t][1]));
            ml1 = fmaxf(ml1, fmaxf(sa[t][2], sa[t][3]));
        }
        ml0 = fmaxf(ml0, __shfl_xor_sync(0xffffffffu, ml0, 1));
        ml0 = fmaxf(ml0, __shfl_xor_sync(0xffffffffu, ml0, 2));
        ml1 = fmaxf(ml1, __shfl_xor_sync(0xffffffffu, ml1, 1));
        ml1 = fmaxf(ml1, __shfl_xor_sync(0xffffffffu, ml1, 2));
        float mn0 = fmaxf(m0, ml0), mn1 = fmaxf(m1, ml1);
        float c0 = __expf(m0 - mn0), c1 = __expf(m1 - mn1);
        m0 = mn0; m1 = mn1;
#pragma unroll
        for (int j = 0; j < 16; j++) {
            out[j][0] *= c0; out[j][1] *= c0;
            out[j][2] *= c1; out[j][3] *= c1;
        }

        // ---- exp -> P frags (hi/lo), row sums ----
        float rs0 = 0.f, rs1 = 0.f;
        uint32_t pah[7][4], pal[7][4];
#pragma unroll
        for (int s2 = 0; s2 < 7; s2++) {
#pragma unroll
            for (int u = 0; u < 2; u++) {
                int t = s2 * 2 + u;
                float p0 = __expf(sa[t][0] - mn0);
                float p1 = __expf(sa[t][1] - mn0);
                float p2 = __expf(sa[t][2] - mn1);
                float p3 = __expf(sa[t][3] - mn1);
                rs0 += p0 + p1; rs1 += p2 + p3;
                __nv_bfloat162 h01 = __floats2bfloat162_rn(p0, p1);
                __nv_bfloat162 h23 = __floats2bfloat162_rn(p2, p3);
                float e0 = p0 - __bfloat162float(h01.x), e1 = p1 - __bfloat162float(h01.y);
                float e2 = p2 - __bfloat162float(h23.x), e3 = p3 - __bfloat162float(h23.y);
                pah[s2][u * 2 + 0] = *(uint32_t*)&h01;
                pah[s2][u * 2 + 1] = *(uint32_t*)&h23;
                pal[s2][u * 2 + 0] = pkbf(e0, e1);
                pal[s2][u * 2 + 1] = pkbf(e2, e3);
            }
        }
        rs0 += __shfl_xor_sync(0xffffffffu, rs0, 1);
        rs0 += __shfl_xor_sync(0xffffffffu, rs0, 2);
        rs1 += __shfl_xor_sync(0xffffffffu, rs1, 1);
        rs1 += __shfl_xor_sync(0xffffffffu, rs1, 2);
        l0s = l0s * c0 + rs0;
        l1s = l1s * c1 + rs1;

        // ---- out += P V (3-term split) ----
#pragma unroll
        for (int j = 0; j < 16; j++) {
#pragma unroll
            for (int s2 = 0; s2 < 7; s2++) {
                uint32_t bvh[2], bvl[2];
                ldsm2t(bvh[0], bvh[1], smem_u32(&SM.Vh[s2 * 16 + (lane & 15)][j * 8]));
                ldsm2t(bvl[0], bvl[1], smem_u32(&SM.Vl[s2 * 16 + (lane & 15)][j * 8]));
                mma16816(out[j], pah[s2], bvh);
                mma16816(out[j], pah[s2], bvl);
                mma16816(out[j], pal[s2], bvh);
            }
        }
    }

    // ---- epilogue ----
    float inv0 = 1.0f / l0s, inv1 = 1.0f / l1s;
    float* ob = g_ao + (size_t)(b * L_ + r0) * (H_ * VD_) + h * VD_;
#pragma unroll
    for (int j = 0; j < 16; j++) {
        int col = j * 8 + tig * 2;
        *(float2*)(ob + col) = make_float2(out[j][0] * inv0, out[j][1] * inv0);
        *(float2*)(ob + (size_t)8 * (H_ * VD_) + col) =
            make_float2(out[j][2] * inv1, out[j][3] * inv1);
    }
}

// ---------------- launch ---------------------------------------------------
extern "C" void kernel_launch(void* const* d_in, const int* in_sizes, int n_in,
                              void* d_out, int out_size) {
    const float* x         = (const float*)d_in[0];   // (16,784,384)
    const float* Wqkv      = (const float*)d_in[1];   // (1536,384)
    const float* Wproj     = (const float*)d_in[2];   // (384,1024)
    const float* bproj     = (const float*)d_in[3];   // (384,)
    const float* ab_table  = (const float*)d_in[4];   // (8,625)
    const int*   bias_idxs = (const int*)d_in[5];     // (625,625)
    float* out = (float*)d_out;

    void* pqkv = nullptr; cudaGetSymbolAddress(&pqkv, g_qkv);
    void* pao  = nullptr; cudaGetSymbolAddress(&pao,  g_ao);

    const int FSM = (int)sizeof(FlashSmem);   // 78848 bytes
    cudaFuncSetAttribute(flash_mma_kernel, cudaFuncAttributeMaxDynamicSharedMemorySize, FSM);

    build_interp_kernel<<<1, 1024>>>();

    const int totAb = H_ * RESI_ * RESI_;
    gather_ab_kernel<<<(totAb + 255) / 256, 256>>>(ab_table, bias_idxs);

    build_bias_kernel<<<(H_ * L_ * L_) / 256, 256>>>();

    dim3 gqkv(QKVN_ / 128, (B_ * L_) / 128);
    mma_gemm_nt<false><<<gqkv, 256>>>(x, Wqkv, nullptr, (float*)pqkv,
                                      B_ * L_, QKVN_, D_);

    dim3 gatt(L_ / FQT, H_, B_);
    flash_mma_kernel<<<gatt, 224, FSM>>>();

    dim3 gproj(D_ / 128, (B_ * L_) / 128);
    mma_gemm_nt<true><<<gproj, 256>>>((const float*)pao, Wproj, bproj, out,
                                      B_ * L_, D_, H_ * VD_);
}